// round 4
// baseline (speedup 1.0000x reference)
#include <cuda_runtime.h>

#define BB 16
#define CL 512
#define QL 64
#define HH 768
#define NEG_INF (-1e30f)

typedef unsigned long long u64;

__device__ __forceinline__ void fma2(u64& d, u64 a, u64 b) {
    asm("fma.rn.f32x2 %0, %1, %2, %0;" : "+l"(d) : "l"(a), "l"(b));
}
__device__ __forceinline__ u64 pack2(float x, float y) {
    u64 r; asm("mov.b64 %0, {%1, %2};" : "=l"(r) : "f"(x), "f"(y)); return r;
}
__device__ __forceinline__ float2 unpack2(u64 v) {
    float2 r; asm("mov.b64 {%0, %1}, %2;" : "=f"(r.x), "=f"(r.y) : "l"(v)); return r;
}

// ---------------- scratch ----------------
__device__ __align__(16) float g_qp[BB * QL * HH];   // q @ W            [B,64,768]
__device__ __align__(16) float g_bq[BB * QL];        // q . b            [B,64]
__device__ __align__(16) float g_s [BB * CL * QL];   // raw logits       [B,512,64]
__device__ __align__(16) float g_s1[BB * CL * QL];   // row softmax      [B,512,64]
__device__ __align__(16) float g_s2[BB * CL * QL];   // col softmax      [B,512,64]
__device__ __align__(16) float g_t [BB * QL * HH];   // s2^T @ c         [B,64,768]

// ---------------- bq[row] = q[row,:] . b ----------------
__global__ void bq_kernel(const float* __restrict__ q, const float* __restrict__ bias) {
    int row  = blockIdx.x * 8 + (threadIdx.x >> 5);
    int lane = threadIdx.x & 31;
    const float* qr = q + row * HH;
    float s = 0.f;
    for (int d = lane; d < HH; d += 32) s += qr[d] * bias[d];
#pragma unroll
    for (int o = 16; o; o >>= 1) s += __shfl_down_sync(0xffffffffu, s, o);
    if (lane == 0) g_bq[row] = s;
}

// ---------------- qp = q @ W   (M=1024, N=768, K=768), f32x2 ----------------
__global__ void qp_gemm(const float* __restrict__ q, const float* __restrict__ W) {
    __shared__ __align__(16) float As2[16][132];  // dup pairs: [k][2m],[2m+1]
    __shared__ __align__(16) float Bs[16][66];
    int tid = threadIdx.x;
    int tx = tid & 15, ty = tid >> 4;
    int tx4 = tx << 2, ty4 = ty << 2, ty8 = ty << 3;
    int mBase = blockIdx.y * 64, nBase = blockIdx.x * 64;
    int lm = tid >> 2, lk = (tid & 3) << 2;
    int bk = tid >> 4, bn = (tid & 15) << 2;
    u64 acc[4][2] = {};
    for (int kt = 0; kt < HH; kt += 16) {
        float4 av = *(const float4*)(q + (mBase + lm) * HH + kt + lk);
        *(u64*)&As2[lk + 0][2 * lm] = pack2(av.x, av.x);
        *(u64*)&As2[lk + 1][2 * lm] = pack2(av.y, av.y);
        *(u64*)&As2[lk + 2][2 * lm] = pack2(av.z, av.z);
        *(u64*)&As2[lk + 3][2 * lm] = pack2(av.w, av.w);
        float4 bv = *(const float4*)(W + (kt + bk) * HH + nBase + bn);
        Bs[bk][bn + 0] = bv.x; Bs[bk][bn + 1] = bv.y;
        Bs[bk][bn + 2] = bv.z; Bs[bk][bn + 3] = bv.w;
        __syncthreads();
#pragma unroll
        for (int k = 0; k < 16; k++) {
            u64 b0 = *(const u64*)&Bs[k][tx4];
            u64 b1 = *(const u64*)&Bs[k][tx4 + 2];
#pragma unroll
            for (int i = 0; i < 4; i++) {
                u64 aa = *(const u64*)&As2[k][ty8 + 2 * i];
                fma2(acc[i][0], aa, b0);
                fma2(acc[i][1], aa, b1);
            }
        }
        __syncthreads();
    }
#pragma unroll
    for (int i = 0; i < 4; i++) {
        float2 p0 = unpack2(acc[i][0]), p1 = unpack2(acc[i][1]);
        float4 o = make_float4(p0.x, p0.y, p1.x, p1.y);
        *(float4*)(g_qp + (mBase + ty4 + i) * HH + nBase + tx4) = o;
    }
}

// ---------------- s_gemm + fused row softmax ----------------
// s[b,c,j] = sum_h c[b,c,h]*qp[b,j,h] + bq[b,j]; writes g_s (raw) and g_s1.
__global__ void s_gemm(const float* __restrict__ c, const int* __restrict__ q_mask) {
    __shared__ __align__(16) float As2[16][132];  // c, dup pairs
    __shared__ __align__(16) float Bs[16][66];    // qp (K-major)
    int tid = threadIdx.x;
    int tx = tid & 15, ty = tid >> 4;
    int tx4 = tx << 2, ty4 = ty << 2, ty8 = ty << 3;
    int b = blockIdx.y;
    int mBase = blockIdx.x * 64;
    const float* A = c + b * CL * HH;
    const float* Bt = g_qp + b * QL * HH;
    int lm = tid >> 2, lk = (tid & 3) << 2;
    u64 acc[4][2] = {};
    for (int kt = 0; kt < HH; kt += 16) {
        float4 av = *(const float4*)(A + (mBase + lm) * HH + kt + lk);
        *(u64*)&As2[lk + 0][2 * lm] = pack2(av.x, av.x);
        *(u64*)&As2[lk + 1][2 * lm] = pack2(av.y, av.y);
        *(u64*)&As2[lk + 2][2 * lm] = pack2(av.z, av.z);
        *(u64*)&As2[lk + 3][2 * lm] = pack2(av.w, av.w);
        float4 bv = *(const float4*)(Bt + lm * HH + kt + lk);   // lm = j row
        Bs[lk + 0][lm] = bv.x; Bs[lk + 1][lm] = bv.y;
        Bs[lk + 2][lm] = bv.z; Bs[lk + 3][lm] = bv.w;
        __syncthreads();
#pragma unroll
        for (int k = 0; k < 16; k++) {
            u64 b0 = *(const u64*)&Bs[k][tx4];
            u64 b1 = *(const u64*)&Bs[k][tx4 + 2];
#pragma unroll
            for (int i = 0; i < 4; i++) {
                u64 aa = *(const u64*)&As2[k][ty8 + 2 * i];
                fma2(acc[i][0], aa, b0);
                fma2(acc[i][1], aa, b1);
            }
        }
        __syncthreads();
    }
    // epilogue: add bias, store raw logits, fused row softmax (16-lane groups)
    float4 bqv = *(const float4*)(g_bq + b * QL + tx4);
    int qm0 = q_mask[b * QL + tx4 + 0];
    int qm1 = q_mask[b * QL + tx4 + 1];
    int qm2 = q_mask[b * QL + tx4 + 2];
    int qm3 = q_mask[b * QL + tx4 + 3];
#pragma unroll
    for (int i = 0; i < 4; i++) {
        float2 p0 = unpack2(acc[i][0]), p1 = unpack2(acc[i][1]);
        float v0 = p0.x + bqv.x, v1 = p0.y + bqv.y;
        float v2 = p1.x + bqv.z, v3 = p1.y + bqv.w;
        int row = b * CL + mBase + ty4 + i;
        *(float4*)(g_s + row * QL + tx4) = make_float4(v0, v1, v2, v3);
        float m0 = qm0 ? v0 : NEG_INF;
        float m1 = qm1 ? v1 : NEG_INF;
        float m2 = qm2 ? v2 : NEG_INF;
        float m3 = qm3 ? v3 : NEG_INF;
        float mx = fmaxf(fmaxf(m0, m1), fmaxf(m2, m3));
#pragma unroll
        for (int o = 8; o; o >>= 1) mx = fmaxf(mx, __shfl_xor_sync(0xffffffffu, mx, o));
        float e0 = __expf(m0 - mx), e1 = __expf(m1 - mx);
        float e2 = __expf(m2 - mx), e3 = __expf(m3 - mx);
        float s = e0 + e1 + e2 + e3;
#pragma unroll
        for (int o = 8; o; o >>= 1) s += __shfl_xor_sync(0xffffffffu, s, o);
        float inv = 1.f / s;
        *(float4*)(g_s1 + row * QL + tx4) = make_float4(e0 * inv, e1 * inv, e2 * inv, e3 * inv);
    }
}

// ---------------- s2: column softmax over c with c_mask ----------------
__global__ void col_softmax(const int* __restrict__ c_mask) {
    int j = blockIdx.x;       // 0..63
    int b = blockIdx.y;       // 0..15
    int t = threadIdx.x;      // 0..127
    int lane = t & 31, w = t >> 5;
    __shared__ float redm[4], reds[4];
    float v[4];
#pragma unroll
    for (int i = 0; i < 4; i++) {
        int crow = t + i * 128;
        v[i] = c_mask[b * CL + crow] ? g_s[(b * CL + crow) * QL + j] : NEG_INF;
    }
    float mx = fmaxf(fmaxf(v[0], v[1]), fmaxf(v[2], v[3]));
#pragma unroll
    for (int o = 16; o; o >>= 1) mx = fmaxf(mx, __shfl_xor_sync(0xffffffffu, mx, o));
    if (lane == 0) redm[w] = mx;
    __syncthreads();
    mx = fmaxf(fmaxf(redm[0], redm[1]), fmaxf(redm[2], redm[3]));
    float e[4]; float s = 0.f;
#pragma unroll
    for (int i = 0; i < 4; i++) { e[i] = __expf(v[i] - mx); s += e[i]; }
#pragma unroll
    for (int o = 16; o; o >>= 1) s += __shfl_xor_sync(0xffffffffu, s, o);
    if (lane == 0) reds[w] = s;
    __syncthreads();
    s = reds[0] + reds[1] + reds[2] + reds[3];
    float inv = 1.f / s;
#pragma unroll
    for (int i = 0; i < 4; i++)
        g_s2[(b * CL + t + i * 128) * QL + j] = e[i] * inv;
}

// ---------------- t[b,j,h] = sum_c s2[b,c,j] * c[b,c,h]  (M=64, N=768, K=512) ----------------
__global__ void t_gemm(const float* __restrict__ c) {
    __shared__ __align__(16) float As2[16][132];  // s2 dup: [kc][2j],[2j+1]
    __shared__ __align__(16) float Bs[16][66];    // c: [kc][h]
    int tid = threadIdx.x;
    int tx = tid & 15, ty = tid >> 4;
    int tx4 = tx << 2, ty4 = ty << 2, ty8 = ty << 3;
    int b = blockIdx.y;
    int nBase = blockIdx.x * 64;
    int bk = tid >> 4;            // 0..15 (k row)
    int q4 = (tid & 15) << 2;     // 0..60
    u64 acc[4][2] = {};
    for (int kt = 0; kt < CL; kt += 16) {
        float4 av = *(const float4*)(g_s2 + (b * CL + kt + bk) * QL + q4);
        *(u64*)&As2[bk][2 * (q4 + 0)] = pack2(av.x, av.x);
        *(u64*)&As2[bk][2 * (q4 + 1)] = pack2(av.y, av.y);
        *(u64*)&As2[bk][2 * (q4 + 2)] = pack2(av.z, av.z);
        *(u64*)&As2[bk][2 * (q4 + 3)] = pack2(av.w, av.w);
        float4 bv = *(const float4*)(c + (b * CL + kt + bk) * HH + nBase + q4);
        Bs[bk][q4 + 0] = bv.x; Bs[bk][q4 + 1] = bv.y;
        Bs[bk][q4 + 2] = bv.z; Bs[bk][q4 + 3] = bv.w;
        __syncthreads();
#pragma unroll
        for (int k = 0; k < 16; k++) {
            u64 b0 = *(const u64*)&Bs[k][tx4];
            u64 b1 = *(const u64*)&Bs[k][tx4 + 2];
#pragma unroll
            for (int i = 0; i < 4; i++) {
                u64 aa = *(const u64*)&As2[k][ty8 + 2 * i];
                fma2(acc[i][0], aa, b0);
                fma2(acc[i][1], aa, b1);
            }
        }
        __syncthreads();
    }
#pragma unroll
    for (int i = 0; i < 4; i++) {
        float2 p0 = unpack2(acc[i][0]), p1 = unpack2(acc[i][1]);
        float4 o = make_float4(p0.x, p0.y, p1.x, p1.y);
        *(float4*)(g_t + (b * QL + ty4 + i) * HH + nBase + tx4) = o;
    }
}

// ---------------- final: a = s1@q, bvec = s1@t, out = [c, a, c*a, c*bvec] ----------------
__global__ void final_kernel(const float* __restrict__ c, const float* __restrict__ q,
                             float* __restrict__ out) {
    __shared__ __align__(16) float S1s[64][65];  // [c][j]
    __shared__ __align__(16) float Buf[64][66];  // [j][h]
    int tid = threadIdx.x;
    int tx = tid & 15, ty = tid >> 4;
    int tx4 = tx << 2, ty4 = ty << 2;
    int b = blockIdx.y;
    int cBase = blockIdx.x * 64;
    int hStart = blockIdx.z * 384;

    int lr  = tid >> 2;            // 0..63
    int lcb = (tid & 3) << 2;      // 0,4,8,12

#pragma unroll
    for (int i = 0; i < 4; i++) {
        int lc = lcb + i * 16;
        float4 sv = *(const float4*)(g_s1 + (b * CL + cBase + lr) * QL + lc);
        S1s[lr][lc + 0] = sv.x; S1s[lr][lc + 1] = sv.y;
        S1s[lr][lc + 2] = sv.z; S1s[lr][lc + 3] = sv.w;
    }
    __syncthreads();

    const float* qb = q + b * QL * HH;
    const float* tb = g_t + b * QL * HH;
    const float* cb = c + b * CL * HH;
    float* ob = out + (size_t)(b * CL) * (4 * HH);

    for (int hc = hStart; hc < hStart + 384; hc += 64) {
        // ---- pass 1: a = s1 @ q ----
#pragma unroll
        for (int i = 0; i < 4; i++) {
            int lc = lcb + i * 16;
            float4 qv = *(const float4*)(qb + lr * HH + hc + lc);
            Buf[lr][lc + 0] = qv.x; Buf[lr][lc + 1] = qv.y;
            Buf[lr][lc + 2] = qv.z; Buf[lr][lc + 3] = qv.w;
        }
        __syncthreads();
        u64 acc[4][2] = {};
#pragma unroll 16
        for (int k = 0; k < 64; k++) {
            u64 b0 = *(const u64*)&Buf[k][tx4];
            u64 b1 = *(const u64*)&Buf[k][tx4 + 2];
#pragma unroll
            for (int i = 0; i < 4; i++) {
                float a = S1s[ty4 + i][k];
                u64 aa = pack2(a, a);
                fma2(acc[i][0], aa, b0);
                fma2(acc[i][1], aa, b1);
            }
        }
#pragma unroll
        for (int i = 0; i < 4; i++) {
            int r = cBase + ty4 + i;
            float4 cv = *(const float4*)(cb + r * HH + hc + tx4);
            float2 p0 = unpack2(acc[i][0]), p1 = unpack2(acc[i][1]);
            float4 a4 = make_float4(p0.x, p0.y, p1.x, p1.y);
            float4 ca = make_float4(cv.x * a4.x, cv.y * a4.y, cv.z * a4.z, cv.w * a4.w);
            float* orow = ob + (size_t)r * (4 * HH);
            *(float4*)(orow + 0 * HH + hc + tx4) = cv;   // c
            *(float4*)(orow + 1 * HH + hc + tx4) = a4;   // a
            *(float4*)(orow + 2 * HH + hc + tx4) = ca;   // c*a
        }
        __syncthreads();
        // ---- pass 2: bvec = s1 @ t ----
#pragma unroll
        for (int i = 0; i < 4; i++) {
            int lc = lcb + i * 16;
            float4 tv = *(const float4*)(tb + lr * HH + hc + lc);
            Buf[lr][lc + 0] = tv.x; Buf[lr][lc + 1] = tv.y;
            Buf[lr][lc + 2] = tv.z; Buf[lr][lc + 3] = tv.w;
        }
        __syncthreads();
        u64 acc2[4][2] = {};
#pragma unroll 16
        for (int k = 0; k < 64; k++) {
            u64 b0 = *(const u64*)&Buf[k][tx4];
            u64 b1 = *(const u64*)&Buf[k][tx4 + 2];
#pragma unroll
            for (int i = 0; i < 4; i++) {
                float a = S1s[ty4 + i][k];
                u64 aa = pack2(a, a);
                fma2(acc2[i][0], aa, b0);
                fma2(acc2[i][1], aa, b1);
            }
        }
#pragma unroll
        for (int i = 0; i < 4; i++) {
            int r = cBase + ty4 + i;
            float4 cv = *(const float4*)(cb + r * HH + hc + tx4);
            float2 p0 = unpack2(acc2[i][0]), p1 = unpack2(acc2[i][1]);
            float4 cbv = make_float4(cv.x * p0.x, cv.y * p0.y, cv.z * p1.x, cv.w * p1.y);
            float* orow = ob + (size_t)r * (4 * HH);
            *(float4*)(orow + 3 * HH + hc + tx4) = cbv;  // c*bvec
        }
        __syncthreads();
    }
}

extern "C" void kernel_launch(void* const* d_in, const int* in_sizes, int n_in,
                              void* d_out, int out_size) {
    (void)in_sizes; (void)n_in; (void)out_size;
    const float* c      = (const float*)d_in[0];
    const float* q      = (const float*)d_in[1];
    const int*   c_mask = (const int*)d_in[2];
    const int*   q_mask = (const int*)d_in[3];
    const float* W      = (const float*)d_in[4];
    const float* bias   = (const float*)d_in[5];
    float* out = (float*)d_out;

    bq_kernel   <<<128, 256>>>(q, bias);
    qp_gemm     <<<dim3(12, 16), 256>>>(q, W);
    s_gemm      <<<dim3(8, 16), 256>>>(c, q_mask);
    col_softmax <<<dim3(64, 16), 128>>>(c_mask);
    t_gemm      <<<dim3(12, 16), 256>>>(c);
    final_kernel<<<dim3(8, 16, 2), 256>>>(c, q, out);
}

// round 6
// speedup vs baseline: 1.0411x; 1.0411x over previous
#include <cuda_runtime.h>

#define BB 16
#define CL 512
#define QL 64
#define HH 768
#define NEG_INF (-1e30f)

typedef unsigned long long u64;

__device__ __forceinline__ void fma2(u64& d, u64 a, u64 b) {
    asm("fma.rn.f32x2 %0, %1, %2, %0;" : "+l"(d) : "l"(a), "l"(b));
}
__device__ __forceinline__ u64 pack2(float x, float y) {
    u64 r; asm("mov.b64 %0, {%1, %2};" : "=l"(r) : "f"(x), "f"(y)); return r;
}
__device__ __forceinline__ float2 unpack2(u64 v) {
    float2 r; asm("mov.b64 {%0, %1}, %2;" : "=f"(r.x), "=f"(r.y) : "l"(v)); return r;
}

// ---------------- scratch ----------------
__device__ __align__(16) float g_qp[BB * QL * HH];   // q @ W            [B,64,768]
__device__ __align__(16) float g_bq[BB * QL];        // q . b            [B,64]
__device__ __align__(16) float g_s [BB * CL * QL];   // raw logits       [B,512,64]
__device__ __align__(16) float g_s1[BB * CL * QL];   // row softmax      [B,512,64]
__device__ __align__(16) float g_s2[BB * CL * QL];   // col softmax      [B,512,64]
__device__ __align__(16) float g_t [BB * QL * HH];   // s2^T @ c         [B,64,768]

// ---------------- bq[row] = q[row,:] . b ----------------
__global__ void bq_kernel(const float* __restrict__ q, const float* __restrict__ bias) {
    int row  = blockIdx.x * 8 + (threadIdx.x >> 5);
    int lane = threadIdx.x & 31;
    const float* qr = q + row * HH;
    float s = 0.f;
    for (int d = lane; d < HH; d += 32) s += qr[d] * bias[d];
#pragma unroll
    for (int o = 16; o; o >>= 1) s += __shfl_down_sync(0xffffffffu, s, o);
    if (lane == 0) g_bq[row] = s;
}

// =====================================================================
// GEMM core layout (all three GEMMs):
//   64x64x16 tile, 128 threads. tx = tid&15, ty = tid>>4 (0..7).
//   Thread owns rows m8 = ty*8 .. +7 (as 4 M-pairs) and cols tx+16j (j=0..3).
//   As[16][68]  : [k][m], m-contiguous -> aPair = LDS.64 (natural M-pair).
//   Bs2[16][132]: [k][2n], dup pairs (b,b) -> bSplat = LDS.64, conflict-free
//                 because cols are strided by 16 across lanes.
//   fma2(acc[i][j], aPair_i, bSplat_j): acc pair = rows (2i,2i+1), col tx+16j.
// =====================================================================

// ---------------- qp = q @ W   (M=1024, N=768, K=768) ----------------
__global__ void qp_gemm(const float* __restrict__ q, const float* __restrict__ W) {
    __shared__ __align__(16) float As[16][68];
    __shared__ __align__(16) float Bs2[16][132];
    int tid = threadIdx.x;
    int tx = tid & 15, ty = tid >> 4;
    int m8 = ty << 3;
    int mBase = blockIdx.y * 64, nBase = blockIdx.x * 64;
    int lm = tid >> 1, lkB = (tid & 1) << 3;       // A transpose fill
    int bk = tid & 15, bnB = (tid >> 4) << 3;      // B dup fill
    u64 acc[4][4] = {};
    for (int kt = 0; kt < HH; kt += 16) {
        float4 a1 = *(const float4*)(q + (mBase + lm) * HH + kt + lkB);
        float4 a2 = *(const float4*)(q + (mBase + lm) * HH + kt + lkB + 4);
        As[lkB + 0][lm] = a1.x; As[lkB + 1][lm] = a1.y;
        As[lkB + 2][lm] = a1.z; As[lkB + 3][lm] = a1.w;
        As[lkB + 4][lm] = a2.x; As[lkB + 5][lm] = a2.y;
        As[lkB + 6][lm] = a2.z; As[lkB + 7][lm] = a2.w;
        float4 b1 = *(const float4*)(W + (kt + bk) * HH + nBase + bnB);
        float4 b2 = *(const float4*)(W + (kt + bk) * HH + nBase + bnB + 4);
        *(u64*)&Bs2[bk][2 * (bnB + 0)] = pack2(b1.x, b1.x);
        *(u64*)&Bs2[bk][2 * (bnB + 1)] = pack2(b1.y, b1.y);
        *(u64*)&Bs2[bk][2 * (bnB + 2)] = pack2(b1.z, b1.z);
        *(u64*)&Bs2[bk][2 * (bnB + 3)] = pack2(b1.w, b1.w);
        *(u64*)&Bs2[bk][2 * (bnB + 4)] = pack2(b2.x, b2.x);
        *(u64*)&Bs2[bk][2 * (bnB + 5)] = pack2(b2.y, b2.y);
        *(u64*)&Bs2[bk][2 * (bnB + 6)] = pack2(b2.z, b2.z);
        *(u64*)&Bs2[bk][2 * (bnB + 7)] = pack2(b2.w, b2.w);
        __syncthreads();
#pragma unroll
        for (int k = 0; k < 16; k++) {
            u64 av[4], bv[4];
#pragma unroll
            for (int i = 0; i < 4; i++) av[i] = *(const u64*)&As[k][m8 + 2 * i];
#pragma unroll
            for (int j = 0; j < 4; j++) bv[j] = *(const u64*)&Bs2[k][2 * (tx + 16 * j)];
#pragma unroll
            for (int i = 0; i < 4; i++)
#pragma unroll
                for (int j = 0; j < 4; j++) fma2(acc[i][j], av[i], bv[j]);
        }
        __syncthreads();
    }
#pragma unroll
    for (int i = 0; i < 4; i++) {
        int r0 = mBase + m8 + 2 * i;
#pragma unroll
        for (int j = 0; j < 4; j++) {
            float2 p = unpack2(acc[i][j]);
            int cc = nBase + tx + 16 * j;
            g_qp[r0 * HH + cc]       = p.x;
            g_qp[(r0 + 1) * HH + cc] = p.y;
        }
    }
}

// ---------------- s_gemm + fused row softmax ----------------
// s[b,c,j] = sum_h c[b,c,h]*qp[b,j,h] + bq[b,j]; writes g_s (raw) and g_s1.
__global__ void s_gemm(const float* __restrict__ c, const int* __restrict__ q_mask) {
    __shared__ __align__(16) float As[16][68];     // c (transposed)
    __shared__ __align__(16) float Bs2[16][132];   // qp dup: [kh][2j]
    int tid = threadIdx.x;
    int tx = tid & 15, ty = tid >> 4;
    int m8 = ty << 3;
    int b = blockIdx.y;
    int mBase = blockIdx.x * 64;
    const float* A = c + b * CL * HH;
    const float* Bt = g_qp + b * QL * HH;
    int lm = tid >> 1, lkB = (tid & 1) << 3;       // A fill
    int lj = tid >> 1;                             // B fill (same pattern)
    u64 acc[4][4] = {};
    for (int kt = 0; kt < HH; kt += 16) {
        float4 a1 = *(const float4*)(A + (mBase + lm) * HH + kt + lkB);
        float4 a2 = *(const float4*)(A + (mBase + lm) * HH + kt + lkB + 4);
        As[lkB + 0][lm] = a1.x; As[lkB + 1][lm] = a1.y;
        As[lkB + 2][lm] = a1.z; As[lkB + 3][lm] = a1.w;
        As[lkB + 4][lm] = a2.x; As[lkB + 5][lm] = a2.y;
        As[lkB + 6][lm] = a2.z; As[lkB + 7][lm] = a2.w;
        float4 b1 = *(const float4*)(Bt + lj * HH + kt + lkB);
        float4 b2 = *(const float4*)(Bt + lj * HH + kt + lkB + 4);
        *(u64*)&Bs2[lkB + 0][2 * lj] = pack2(b1.x, b1.x);
        *(u64*)&Bs2[lkB + 1][2 * lj] = pack2(b1.y, b1.y);
        *(u64*)&Bs2[lkB + 2][2 * lj] = pack2(b1.z, b1.z);
        *(u64*)&Bs2[lkB + 3][2 * lj] = pack2(b1.w, b1.w);
        *(u64*)&Bs2[lkB + 4][2 * lj] = pack2(b2.x, b2.x);
        *(u64*)&Bs2[lkB + 5][2 * lj] = pack2(b2.y, b2.y);
        *(u64*)&Bs2[lkB + 6][2 * lj] = pack2(b2.z, b2.z);
        *(u64*)&Bs2[lkB + 7][2 * lj] = pack2(b2.w, b2.w);
        __syncthreads();
#pragma unroll
        for (int k = 0; k < 16; k++) {
            u64 av[4], bv[4];
#pragma unroll
            for (int i = 0; i < 4; i++) av[i] = *(const u64*)&As[k][m8 + 2 * i];
#pragma unroll
            for (int j = 0; j < 4; j++) bv[j] = *(const u64*)&Bs2[k][2 * (tx + 16 * j)];
#pragma unroll
            for (int i = 0; i < 4; i++)
#pragma unroll
                for (int j = 0; j < 4; j++) fma2(acc[i][j], av[i], bv[j]);
        }
        __syncthreads();
    }
    // epilogue: bias add, raw store, fused row softmax (16-lane half-warp groups)
    float bqv[4]; int qm[4];
#pragma unroll
    for (int j = 0; j < 4; j++) {
        int col = tx + 16 * j;
        bqv[j] = g_bq[b * QL + col];
        qm[j]  = q_mask[b * QL + col];
    }
#pragma unroll
    for (int i = 0; i < 4; i++) {
        float2 p[4];
#pragma unroll
        for (int j = 0; j < 4; j++) p[j] = unpack2(acc[i][j]);
#pragma unroll
        for (int half = 0; half < 2; half++) {
            int row = b * CL + mBase + m8 + 2 * i + half;
            float v[4];
#pragma unroll
            for (int j = 0; j < 4; j++) v[j] = (half ? p[j].y : p[j].x) + bqv[j];
            float m0 = qm[0] ? v[0] : NEG_INF;
            float m1 = qm[1] ? v[1] : NEG_INF;
            float m2 = qm[2] ? v[2] : NEG_INF;
            float m3 = qm[3] ? v[3] : NEG_INF;
            float mx = fmaxf(fmaxf(m0, m1), fmaxf(m2, m3));
#pragma unroll
            for (int o = 8; o; o >>= 1) mx = fmaxf(mx, __shfl_xor_sync(0xffffffffu, mx, o));
            float e0 = __expf(m0 - mx), e1 = __expf(m1 - mx);
            float e2 = __expf(m2 - mx), e3 = __expf(m3 - mx);
            float ss = e0 + e1 + e2 + e3;
#pragma unroll
            for (int o = 8; o; o >>= 1) ss += __shfl_xor_sync(0xffffffffu, ss, o);
            float inv = 1.f / ss;
            g_s [row * QL + tx]      = v[0];
            g_s [row * QL + tx + 16] = v[1];
            g_s [row * QL + tx + 32] = v[2];
            g_s [row * QL + tx + 48] = v[3];
            g_s1[row * QL + tx]      = e0 * inv;
            g_s1[row * QL + tx + 16] = e1 * inv;
            g_s1[row * QL + tx + 32] = e2 * inv;
            g_s1[row * QL + tx + 48] = e3 * inv;
        }
    }
}

// ---------------- s2: column softmax over c with c_mask ----------------
__global__ void col_softmax(const int* __restrict__ c_mask) {
    int j = blockIdx.x;       // 0..63
    int b = blockIdx.y;       // 0..15
    int t = threadIdx.x;      // 0..127
    int lane = t & 31, w = t >> 5;
    __shared__ float redm[4], reds[4];
    float v[4];
#pragma unroll
    for (int i = 0; i < 4; i++) {
        int crow = t + i * 128;
        v[i] = c_mask[b * CL + crow] ? g_s[(b * CL + crow) * QL + j] : NEG_INF;
    }
    float mx = fmaxf(fmaxf(v[0], v[1]), fmaxf(v[2], v[3]));
#pragma unroll
    for (int o = 16; o; o >>= 1) mx = fmaxf(mx, __shfl_xor_sync(0xffffffffu, mx, o));
    if (lane == 0) redm[w] = mx;
    __syncthreads();
    mx = fmaxf(fmaxf(redm[0], redm[1]), fmaxf(redm[2], redm[3]));
    float e[4]; float s = 0.f;
#pragma unroll
    for (int i = 0; i < 4; i++) { e[i] = __expf(v[i] - mx); s += e[i]; }
#pragma unroll
    for (int o = 16; o; o >>= 1) s += __shfl_xor_sync(0xffffffffu, s, o);
    if (lane == 0) reds[w] = s;
    __syncthreads();
    s = reds[0] + reds[1] + reds[2] + reds[3];
    float inv = 1.f / s;
#pragma unroll
    for (int i = 0; i < 4; i++)
        g_s2[(b * CL + t + i * 128) * QL + j] = e[i] * inv;
}

// ---------------- t[b,j,h] = sum_c s2[b,c,j] * c[b,c,h]  (M=64, N=768, K=512) ----------------
__global__ void t_gemm(const float* __restrict__ c) {
    __shared__ __align__(16) float As[16][68];     // [kc][j] natural from s2
    __shared__ __align__(16) float Bs2[16][132];   // c dup: [kc][2h]
    int tid = threadIdx.x;
    int tx = tid & 15, ty = tid >> 4;
    int m8 = ty << 3;
    int b = blockIdx.y;
    int nBase = blockIdx.x * 64;
    int lc = tid >> 3, ljB = (tid & 7) << 3;       // A fill (natural copy)
    int bk = tid & 15, bnB = (tid >> 4) << 3;      // B dup fill
    u64 acc[4][4] = {};
    for (int kt = 0; kt < CL; kt += 16) {
        float4 a1 = *(const float4*)(g_s2 + (b * CL + kt + lc) * QL + ljB);
        float4 a2 = *(const float4*)(g_s2 + (b * CL + kt + lc) * QL + ljB + 4);
        *(float4*)&As[lc][ljB]     = a1;
        *(float4*)&As[lc][ljB + 4] = a2;
        float4 b1 = *(const float4*)(c + (b * CL + kt + bk) * HH + nBase + bnB);
        float4 b2 = *(const float4*)(c + (b * CL + kt + bk) * HH + nBase + bnB + 4);
        *(u64*)&Bs2[bk][2 * (bnB + 0)] = pack2(b1.x, b1.x);
        *(u64*)&Bs2[bk][2 * (bnB + 1)] = pack2(b1.y, b1.y);
        *(u64*)&Bs2[bk][2 * (bnB + 2)] = pack2(b1.z, b1.z);
        *(u64*)&Bs2[bk][2 * (bnB + 3)] = pack2(b1.w, b1.w);
        *(u64*)&Bs2[bk][2 * (bnB + 4)] = pack2(b2.x, b2.x);
        *(u64*)&Bs2[bk][2 * (bnB + 5)] = pack2(b2.y, b2.y);
        *(u64*)&Bs2[bk][2 * (bnB + 6)] = pack2(b2.z, b2.z);
        *(u64*)&Bs2[bk][2 * (bnB + 7)] = pack2(b2.w, b2.w);
        __syncthreads();
#pragma unroll
        for (int k = 0; k < 16; k++) {
            u64 av[4], bv[4];
#pragma unroll
            for (int i = 0; i < 4; i++) av[i] = *(const u64*)&As[k][m8 + 2 * i];
#pragma unroll
            for (int j = 0; j < 4; j++) bv[j] = *(const u64*)&Bs2[k][2 * (tx + 16 * j)];
#pragma unroll
            for (int i = 0; i < 4; i++)
#pragma unroll
                for (int j = 0; j < 4; j++) fma2(acc[i][j], av[i], bv[j]);
        }
        __syncthreads();
    }
#pragma unroll
    for (int i = 0; i < 4; i++) {
        int r0 = b * QL + m8 + 2 * i;
#pragma unroll
        for (int j = 0; j < 4; j++) {
            float2 p = unpack2(acc[i][j]);
            int cc = nBase + tx + 16 * j;
            g_t[r0 * HH + cc]       = p.x;
            g_t[(r0 + 1) * HH + cc] = p.y;
        }
    }
}

// ---------------- final: a = s1@q, bvec = s1@t, out = [c, a, c*a, c*bvec] ----------------
__global__ void final_kernel(const float* __restrict__ c, const float* __restrict__ q,
                             float* __restrict__ out) {
    __shared__ float S1s[64][65];  // [c][j]
    __shared__ float Buf[64][66];  // [j][h]
    int tid = threadIdx.x;
    int tx = tid & 15, ty = tid >> 4;
    int tx4 = tx << 2, ty4 = ty << 2;
    int b = blockIdx.y;
    int cBase = blockIdx.x * 64;
    int hStart = blockIdx.z * 384;

    int lr  = tid >> 2;            // 0..63
    int lcb = (tid & 3) << 2;      // 0,4,8,12

#pragma unroll
    for (int i = 0; i < 4; i++) {
        int lc = lcb + i * 16;
        float4 sv = *(const float4*)(g_s1 + (b * CL + cBase + lr) * QL + lc);
        S1s[lr][lc + 0] = sv.x; S1s[lr][lc + 1] = sv.y;
        S1s[lr][lc + 2] = sv.z; S1s[lr][lc + 3] = sv.w;
    }
    __syncthreads();

    const float* qb = q + b * QL * HH;
    const float* tb = g_t + b * QL * HH;
    const float* cb = c + b * CL * HH;
    float* ob = out + (size_t)(b * CL) * (4 * HH);

    for (int hc = hStart; hc < hStart + 384; hc += 64) {
        // ---- pass 1: a = s1 @ q ----
#pragma unroll
        for (int i = 0; i < 4; i++) {
            int lc = lcb + i * 16;
            float4 qv = *(const float4*)(qb + lr * HH + hc + lc);
            Buf[lr][lc + 0] = qv.x; Buf[lr][lc + 1] = qv.y;
            Buf[lr][lc + 2] = qv.z; Buf[lr][lc + 3] = qv.w;
        }
        __syncthreads();
        float acc[4][4] = {};
#pragma unroll 16
        for (int k = 0; k < 64; k++) {
            float ar[4], br[4];
#pragma unroll
            for (int i = 0; i < 4; i++) ar[i] = S1s[ty4 + i][k];
#pragma unroll
            for (int j = 0; j < 4; j++) br[j] = Buf[k][tx4 + j];
#pragma unroll
            for (int i = 0; i < 4; i++)
#pragma unroll
                for (int j = 0; j < 4; j++) acc[i][j] = fmaf(ar[i], br[j], acc[i][j]);
        }
#pragma unroll
        for (int i = 0; i < 4; i++) {
            int r = cBase + ty4 + i;
            float4 cv = *(const float4*)(cb + r * HH + hc + tx4);
            float4 a4 = make_float4(acc[i][0], acc[i][1], acc[i][2], acc[i][3]);
            float4 ca = make_float4(cv.x * a4.x, cv.y * a4.y, cv.z * a4.z, cv.w * a4.w);
            float* orow = ob + (size_t)r * (4 * HH);
            *(float4*)(orow + 0 * HH + hc + tx4) = cv;   // c
            *(float4*)(orow + 1 * HH + hc + tx4) = a4;   // a
            *(float4*)(orow + 2 * HH + hc + tx4) = ca;   // c*a
        }
        __syncthreads();
        // ---- pass 2: bvec = s1 @ t ----
#pragma unroll
        for (int i = 0; i < 4; i++) {
            int lc = lcb + i * 16;
            float4 tv = *(const float4*)(tb + lr * HH + hc + lc);
            Buf[lr][lc + 0] = tv.x; Buf[lr][lc + 1] = tv.y;
            Buf[lr][lc + 2] = tv.z; Buf[lr][lc + 3] = tv.w;
        }
        __syncthreads();
        float acc2[4][4] = {};
#pragma unroll 16
        for (int k = 0; k < 64; k++) {
            float ar[4], br[4];
#pragma unroll
            for (int i = 0; i < 4; i++) ar[i] = S1s[ty4 + i][k];
#pragma unroll
            for (int j = 0; j < 4; j++) br[j] = Buf[k][tx4 + j];
#pragma unroll
            for (int i = 0; i < 4; i++)
#pragma unroll
                for (int j = 0; j < 4; j++) acc2[i][j] = fmaf(ar[i], br[j], acc2[i][j]);
        }
#pragma unroll
        for (int i = 0; i < 4; i++) {
            int r = cBase + ty4 + i;
            float4 cv = *(const float4*)(cb + r * HH + hc + tx4);
            float4 cbv = make_float4(cv.x * acc2[i][0], cv.y * acc2[i][1],
                                     cv.z * acc2[i][2], cv.w * acc2[i][3]);
            float* orow = ob + (size_t)r * (4 * HH);
            *(float4*)(orow + 3 * HH + hc + tx4) = cbv;  // c*bvec
        }
        __syncthreads();
    }
}

extern "C" void kernel_launch(void* const* d_in, const int* in_sizes, int n_in,
                              void* d_out, int out_size) {
    (void)in_sizes; (void)n_in; (void)out_size;
    const float* c      = (const float*)d_in[0];
    const float* q      = (const float*)d_in[1];
    const int*   c_mask = (const int*)d_in[2];
    const int*   q_mask = (const int*)d_in[3];
    const float* W      = (const float*)d_in[4];
    const float* bias   = (const float*)d_in[5];
    float* out = (float*)d_out;

    bq_kernel   <<<128, 256>>>(q, bias);
    qp_gemm     <<<dim3(12, 16), 128>>>(q, W);
    s_gemm      <<<dim3(8, 16), 128>>>(c, q_mask);
    col_softmax <<<dim3(64, 16), 128>>>(c_mask);
    t_gemm      <<<dim3(12, 16), 128>>>(c);
    final_kernel<<<dim3(8, 16, 2), 256>>>(c, q, out);
}

// round 7
// speedup vs baseline: 1.3258x; 1.2734x over previous
#include <cuda_runtime.h>
#include <float.h>

#define BB 16
#define CL 512
#define QL 64
#define HH 768
#define NEG_INF (-1e30f)

// ---------------- scratch ----------------
__device__ __align__(16) float g_qp[BB * QL * HH];   // q @ W            [B,64,768]
__device__ __align__(16) float g_bq[BB * QL];        // q . b            [B,64]
__device__ __align__(16) float g_s [BB * CL * QL];   // raw logits       [B,512,64]
__device__ __align__(16) float g_s1[BB * CL * QL];   // row softmax      [B,512,64]
__device__ __align__(16) float g_s2[BB * CL * QL];   // col exp (unnorm) [B,512,64]
__device__ __align__(16) float g_cinv[BB * QL];      // 1/col-sum        [B,64]
__device__ __align__(16) float g_t [BB * QL * HH];   // s2^T @ c         [B,64,768]

// ---------------- bq[row] = q[row,:] . b  (split in two launches) ----------------
__global__ void bq_kernel(const float* __restrict__ q, const float* __restrict__ bias,
                          int rowOffset) {
    int row  = rowOffset + blockIdx.x * 8 + (threadIdx.x >> 5);
    int lane = threadIdx.x & 31;
    const float* qr = q + row * HH;
    float s = 0.f;
    for (int d = lane; d < HH; d += 32) s += qr[d] * bias[d];
#pragma unroll
    for (int o = 16; o; o >>= 1) s += __shfl_down_sync(0xffffffffu, s, o);
    if (lane == 0) g_bq[row] = s;
}

// =====================================================================
// GEMM template: 64x64x16 tile, 256 threads, 4x4 microtile, DOUBLE-BUFFERED
// (one __syncthreads per k-tile; next tile's global loads overlap compute).
// =====================================================================

// ---------------- qp = q @ W   (M=1024, N=768, K=768) ----------------
__global__ void qp_gemm(const float* __restrict__ q, const float* __restrict__ W) {
    __shared__ float As[2][16][68];   // [k][m]
    __shared__ float Bs[2][16][68];   // [k][n]
    int tid = threadIdx.x;
    int tx = tid & 15, ty = tid >> 4;
    int tx4 = tx << 2, ty4 = ty << 2;
    int mBase = blockIdx.y * 64, nBase = blockIdx.x * 64;
    int lm = tid >> 2, lk = (tid & 3) << 2;        // A fill (transpose)
    int bk = tid >> 4, bn4 = (tid & 15) << 2;      // B fill (direct)
    float acc[4][4] = {};

    float4 av = *(const float4*)(q + (mBase + lm) * HH + lk);
    float4 bv = *(const float4*)(W + bk * HH + nBase + bn4);
    As[0][lk + 0][lm] = av.x; As[0][lk + 1][lm] = av.y;
    As[0][lk + 2][lm] = av.z; As[0][lk + 3][lm] = av.w;
    *(float4*)&Bs[0][bk][bn4] = bv;
    __syncthreads();
    int buf = 0;
    for (int kt = 0; kt < HH; kt += 16) {
        bool more = (kt + 16) < HH;
        float4 nav, nbv;
        if (more) {
            nav = *(const float4*)(q + (mBase + lm) * HH + kt + 16 + lk);
            nbv = *(const float4*)(W + (kt + 16 + bk) * HH + nBase + bn4);
        }
#pragma unroll
        for (int k = 0; k < 16; k++) {
            float ar[4], br[4];
#pragma unroll
            for (int i = 0; i < 4; i++) ar[i] = As[buf][k][ty4 + i];
#pragma unroll
            for (int j = 0; j < 4; j++) br[j] = Bs[buf][k][tx4 + j];
#pragma unroll
            for (int i = 0; i < 4; i++)
#pragma unroll
                for (int j = 0; j < 4; j++) acc[i][j] = fmaf(ar[i], br[j], acc[i][j]);
        }
        if (more) {
            int nb = buf ^ 1;
            As[nb][lk + 0][lm] = nav.x; As[nb][lk + 1][lm] = nav.y;
            As[nb][lk + 2][lm] = nav.z; As[nb][lk + 3][lm] = nav.w;
            *(float4*)&Bs[nb][bk][bn4] = nbv;
            __syncthreads();
            buf = nb;
        }
    }
#pragma unroll
    for (int i = 0; i < 4; i++) {
        float4 o = make_float4(acc[i][0], acc[i][1], acc[i][2], acc[i][3]);
        *(float4*)(g_qp + (mBase + ty4 + i) * HH + nBase + tx4) = o;
    }
}

// ---------------- s_gemm + fused row softmax ----------------
// s[b,c,j] = sum_h c[b,c,h]*qp[b,j,h] + bq[b,j]; writes g_s (raw) and g_s1.
__global__ void s_gemm(const float* __restrict__ c, const int* __restrict__ q_mask) {
    __shared__ float As[2][16][68];   // c (transposed)   [k][m]
    __shared__ float Bs[2][16][68];   // qp (transposed)  [k][j]
    int tid = threadIdx.x;
    int tx = tid & 15, ty = tid >> 4;
    int tx4 = tx << 2, ty4 = ty << 2;
    int b = blockIdx.y;
    int mBase = blockIdx.x * 64;
    const float* A = c + b * CL * HH;
    const float* Bt = g_qp + b * QL * HH;
    int lm = tid >> 2, lk = (tid & 3) << 2;
    float acc[4][4] = {};

    float4 av = *(const float4*)(A + (mBase + lm) * HH + lk);
    float4 bv = *(const float4*)(Bt + lm * HH + lk);   // lm = j row
    As[0][lk + 0][lm] = av.x; As[0][lk + 1][lm] = av.y;
    As[0][lk + 2][lm] = av.z; As[0][lk + 3][lm] = av.w;
    Bs[0][lk + 0][lm] = bv.x; Bs[0][lk + 1][lm] = bv.y;
    Bs[0][lk + 2][lm] = bv.z; Bs[0][lk + 3][lm] = bv.w;
    __syncthreads();
    int buf = 0;
    for (int kt = 0; kt < HH; kt += 16) {
        bool more = (kt + 16) < HH;
        float4 nav, nbv;
        if (more) {
            nav = *(const float4*)(A + (mBase + lm) * HH + kt + 16 + lk);
            nbv = *(const float4*)(Bt + lm * HH + kt + 16 + lk);
        }
#pragma unroll
        for (int k = 0; k < 16; k++) {
            float ar[4], br[4];
#pragma unroll
            for (int i = 0; i < 4; i++) ar[i] = As[buf][k][ty4 + i];
#pragma unroll
            for (int j = 0; j < 4; j++) br[j] = Bs[buf][k][tx4 + j];
#pragma unroll
            for (int i = 0; i < 4; i++)
#pragma unroll
                for (int j = 0; j < 4; j++) acc[i][j] = fmaf(ar[i], br[j], acc[i][j]);
        }
        if (more) {
            int nb = buf ^ 1;
            As[nb][lk + 0][lm] = nav.x; As[nb][lk + 1][lm] = nav.y;
            As[nb][lk + 2][lm] = nav.z; As[nb][lk + 3][lm] = nav.w;
            Bs[nb][lk + 0][lm] = nbv.x; Bs[nb][lk + 1][lm] = nbv.y;
            Bs[nb][lk + 2][lm] = nbv.z; Bs[nb][lk + 3][lm] = nbv.w;
            __syncthreads();
            buf = nb;
        }
    }
    // epilogue: bias, raw store, fused row softmax.
    // Row (ty4+i) is owned by the 16 threads tx=0..15 sharing ty = one half-warp.
    float4 bqv = *(const float4*)(g_bq + b * QL + tx4);
    int qm0 = q_mask[b * QL + tx4 + 0];
    int qm1 = q_mask[b * QL + tx4 + 1];
    int qm2 = q_mask[b * QL + tx4 + 2];
    int qm3 = q_mask[b * QL + tx4 + 3];
#pragma unroll
    for (int i = 0; i < 4; i++) {
        float v0 = acc[i][0] + bqv.x, v1 = acc[i][1] + bqv.y;
        float v2 = acc[i][2] + bqv.z, v3 = acc[i][3] + bqv.w;
        int row = b * CL + mBase + ty4 + i;
        *(float4*)(g_s + row * QL + tx4) = make_float4(v0, v1, v2, v3);
        float m0 = qm0 ? v0 : NEG_INF;
        float m1 = qm1 ? v1 : NEG_INF;
        float m2 = qm2 ? v2 : NEG_INF;
        float m3 = qm3 ? v3 : NEG_INF;
        float mx = fmaxf(fmaxf(m0, m1), fmaxf(m2, m3));
#pragma unroll
        for (int o = 8; o; o >>= 1) mx = fmaxf(mx, __shfl_xor_sync(0xffffffffu, mx, o));
        float e0 = __expf(m0 - mx), e1 = __expf(m1 - mx);
        float e2 = __expf(m2 - mx), e3 = __expf(m3 - mx);
        float s = e0 + e1 + e2 + e3;
#pragma unroll
        for (int o = 8; o; o >>= 1) s += __shfl_xor_sync(0xffffffffu, s, o);
        float inv = 1.f / s;
        *(float4*)(g_s1 + row * QL + tx4) = make_float4(e0 * inv, e1 * inv, e2 * inv, e3 * inv);
    }
}

// ---------------- colexp: per-batch column max + exp + 1/sum ----------------
// Writes g_s2 = exp(masked_s - colmax) (unnormalized), g_cinv = 1/colsum.
// t_gemm applies g_cinv during its A-tile load.
__global__ void colexp_kernel(const int* __restrict__ c_mask) {
    int b = blockIdx.x;                 // 0..15
    int tid = threadIdx.x;              // 0..511
    int cg = tid & 15;                  // col group: cols cg*4..cg*4+3
    int ry = tid >> 4;                  // 0..31
    __shared__ float4 red[32][16];
    const float* sp = g_s + b * CL * QL;
    const int*   mp = c_mask + b * CL;

    // pass 1: column max over masked rows
    float4 mx = make_float4(NEG_INF, NEG_INF, NEG_INF, NEG_INF);
#pragma unroll
    for (int k = 0; k < 16; k++) {
        int r = ry + k * 32;
        float4 v = *(const float4*)(sp + r * QL + cg * 4);
        if (!mp[r]) v = make_float4(NEG_INF, NEG_INF, NEG_INF, NEG_INF);
        mx.x = fmaxf(mx.x, v.x); mx.y = fmaxf(mx.y, v.y);
        mx.z = fmaxf(mx.z, v.z); mx.w = fmaxf(mx.w, v.w);
    }
    red[ry][cg] = mx;
    __syncthreads();
#pragma unroll
    for (int st = 16; st >= 1; st >>= 1) {
        if (ry < st) {
            float4 a = red[ry][cg], c2 = red[ry + st][cg];
            a.x = fmaxf(a.x, c2.x); a.y = fmaxf(a.y, c2.y);
            a.z = fmaxf(a.z, c2.z); a.w = fmaxf(a.w, c2.w);
            red[ry][cg] = a;
        }
        __syncthreads();
    }
    float4 cmax = red[0][cg];
    __syncthreads();

    // pass 2: exp + sum
    float4 sm = make_float4(0.f, 0.f, 0.f, 0.f);
    float* op = g_s2 + b * CL * QL;
#pragma unroll
    for (int k = 0; k < 16; k++) {
        int r = ry + k * 32;
        float4 v = *(const float4*)(sp + r * QL + cg * 4);
        if (!mp[r]) v = make_float4(NEG_INF, NEG_INF, NEG_INF, NEG_INF);
        float4 e;
        e.x = __expf(v.x - cmax.x); e.y = __expf(v.y - cmax.y);
        e.z = __expf(v.z - cmax.z); e.w = __expf(v.w - cmax.w);
        *(float4*)(op + r * QL + cg * 4) = e;
        sm.x += e.x; sm.y += e.y; sm.z += e.z; sm.w += e.w;
    }
    red[ry][cg] = sm;
    __syncthreads();
#pragma unroll
    for (int st = 16; st >= 1; st >>= 1) {
        if (ry < st) {
            float4 a = red[ry][cg], c2 = red[ry + st][cg];
            a.x += c2.x; a.y += c2.y; a.z += c2.z; a.w += c2.w;
            red[ry][cg] = a;
        }
        __syncthreads();
    }
    if (ry == 0) {
        float4 s = red[0][cg];
        float4 inv = make_float4(1.f / s.x, 1.f / s.y, 1.f / s.z, 1.f / s.w);
        *(float4*)(g_cinv + b * QL + cg * 4) = inv;
    }
}

// ---------------- t[b,j,h] = sum_c s2n[b,c,j] * c[b,c,h]  (M=64, N=768, K=512) ----------------
// s2n = g_s2 * g_cinv[j], applied during the A-tile load.
__global__ void t_gemm(const float* __restrict__ c) {
    __shared__ float As[2][16][68];   // [kc][j], scaled
    __shared__ float Bs[2][16][68];   // [kc][h]
    int tid = threadIdx.x;
    int tx = tid & 15, ty = tid >> 4;
    int tx4 = tx << 2, ty4 = ty << 2;
    int b = blockIdx.y;
    int nBase = blockIdx.x * 64;
    int lc = tid >> 4, lj4 = (tid & 15) << 2;      // A fill (direct)
    int bk = tid >> 4, bn4 = (tid & 15) << 2;      // B fill (direct)
    float4 inv4 = *(const float4*)(g_cinv + b * QL + lj4);
    float acc[4][4] = {};

    float4 av = *(const float4*)(g_s2 + (b * CL + lc) * QL + lj4);
    av.x *= inv4.x; av.y *= inv4.y; av.z *= inv4.z; av.w *= inv4.w;
    float4 bv = *(const float4*)(c + (b * CL + bk) * HH + nBase + bn4);
    *(float4*)&As[0][lc][lj4] = av;
    *(float4*)&Bs[0][bk][bn4] = bv;
    __syncthreads();
    int buf = 0;
    for (int kt = 0; kt < CL; kt += 16) {
        bool more = (kt + 16) < CL;
        float4 nav, nbv;
        if (more) {
            nav = *(const float4*)(g_s2 + (b * CL + kt + 16 + lc) * QL + lj4);
            nav.x *= inv4.x; nav.y *= inv4.y; nav.z *= inv4.z; nav.w *= inv4.w;
            nbv = *(const float4*)(c + (b * CL + kt + 16 + bk) * HH + nBase + bn4);
        }
#pragma unroll
        for (int k = 0; k < 16; k++) {
            float ar[4], br[4];
#pragma unroll
            for (int i = 0; i < 4; i++) ar[i] = As[buf][k][ty4 + i];
#pragma unroll
            for (int j = 0; j < 4; j++) br[j] = Bs[buf][k][tx4 + j];
#pragma unroll
            for (int i = 0; i < 4; i++)
#pragma unroll
                for (int j = 0; j < 4; j++) acc[i][j] = fmaf(ar[i], br[j], acc[i][j]);
        }
        if (more) {
            int nb = buf ^ 1;
            *(float4*)&As[nb][lc][lj4] = nav;
            *(float4*)&Bs[nb][bk][bn4] = nbv;
            __syncthreads();
            buf = nb;
        }
    }
#pragma unroll
    for (int i = 0; i < 4; i++) {
        float4 o = make_float4(acc[i][0], acc[i][1], acc[i][2], acc[i][3]);
        *(float4*)(g_t + (b * QL + ty4 + i) * HH + nBase + tx4) = o;
    }
}

// ---------------- final: a = s1@q, bvec = s1@t, out = [c, a, c*a, c*bvec] ----------------
__global__ void final_kernel(const float* __restrict__ c, const float* __restrict__ q,
                             float* __restrict__ out) {
    __shared__ float S1s[64][65];  // [c][j]
    __shared__ float Buf[64][66];  // [j][h]
    int tid = threadIdx.x;
    int tx = tid & 15, ty = tid >> 4;
    int tx4 = tx << 2, ty4 = ty << 2;
    int b = blockIdx.y;
    int cBase = blockIdx.x * 64;
    int hStart = blockIdx.z * 384;

    int lr  = tid >> 2;            // 0..63
    int lcb = (tid & 3) << 2;      // 0,4,8,12

#pragma unroll
    for (int i = 0; i < 4; i++) {
        int lc = lcb + i * 16;
        float4 sv = *(const float4*)(g_s1 + (b * CL + cBase + lr) * QL + lc);
        S1s[lr][lc + 0] = sv.x; S1s[lr][lc + 1] = sv.y;
        S1s[lr][lc + 2] = sv.z; S1s[lr][lc + 3] = sv.w;
    }
    __syncthreads();

    const float* qb = q + b * QL * HH;
    const float* tb = g_t + b * QL * HH;
    const float* cb = c + b * CL * HH;
    float* ob = out + (size_t)(b * CL) * (4 * HH);

    for (int hc = hStart; hc < hStart + 384; hc += 64) {
        // ---- pass 1: a = s1 @ q ----
#pragma unroll
        for (int i = 0; i < 4; i++) {
            int lc = lcb + i * 16;
            float4 qv = *(const float4*)(qb + lr * HH + hc + lc);
            Buf[lr][lc + 0] = qv.x; Buf[lr][lc + 1] = qv.y;
            Buf[lr][lc + 2] = qv.z; Buf[lr][lc + 3] = qv.w;
        }
        __syncthreads();
        float acc[4][4] = {};
#pragma unroll 16
        for (int k = 0; k < 64; k++) {
            float ar[4], br[4];
#pragma unroll
            for (int i = 0; i < 4; i++) ar[i] = S1s[ty4 + i][k];
#pragma unroll
            for (int j = 0; j < 4; j++) br[j] = Buf[k][tx4 + j];
#pragma unroll
            for (int i = 0; i < 4; i++)
#pragma unroll
                for (int j = 0; j < 4; j++) acc[i][j] = fmaf(ar[i], br[j], acc[i][j]);
        }
#pragma unroll
        for (int i = 0; i < 4; i++) {
            int r = cBase + ty4 + i;
            float4 cv = *(const float4*)(cb + r * HH + hc + tx4);
            float4 a4 = make_float4(acc[i][0], acc[i][1], acc[i][2], acc[i][3]);
            float4 ca = make_float4(cv.x * a4.x, cv.y * a4.y, cv.z * a4.z, cv.w * a4.w);
            float* orow = ob + (size_t)r * (4 * HH);
            *(float4*)(orow + 0 * HH + hc + tx4) = cv;   // c
            *(float4*)(orow + 1 * HH + hc + tx4) = a4;   // a
            *(float4*)(orow + 2 * HH + hc + tx4) = ca;   // c*a
        }
        __syncthreads();
        // ---- pass 2: bvec = s1 @ t ----
#pragma unroll
        for (int i = 0; i < 4; i++) {
            int lc = lcb + i * 16;
            float4 tv = *(const float4*)(tb + lr * HH + hc + lc);
            Buf[lr][lc + 0] = tv.x; Buf[lr][lc + 1] = tv.y;
            Buf[lr][lc + 2] = tv.z; Buf[lr][lc + 3] = tv.w;
        }
        __syncthreads();
        float acc2[4][4] = {};
#pragma unroll 16
        for (int k = 0; k < 64; k++) {
            float ar[4], br[4];
#pragma unroll
            for (int i = 0; i < 4; i++) ar[i] = S1s[ty4 + i][k];
#pragma unroll
            for (int j = 0; j < 4; j++) br[j] = Buf[k][tx4 + j];
#pragma unroll
            for (int i = 0; i < 4; i++)
#pragma unroll
                for (int j = 0; j < 4; j++) acc2[i][j] = fmaf(ar[i], br[j], acc2[i][j]);
        }
#pragma unroll
        for (int i = 0; i < 4; i++) {
            int r = cBase + ty4 + i;
            float4 cv = *(const float4*)(cb + r * HH + hc + tx4);
            float4 cbv = make_float4(cv.x * acc2[i][0], cv.y * acc2[i][1],
                                     cv.z * acc2[i][2], cv.w * acc2[i][3]);
            float* orow = ob + (size_t)r * (4 * HH);
            *(float4*)(orow + 3 * HH + hc + tx4) = cbv;  // c*bvec
        }
        __syncthreads();
    }
}

extern "C" void kernel_launch(void* const* d_in, const int* in_sizes, int n_in,
                              void* d_out, int out_size) {
    (void)in_sizes; (void)n_in; (void)out_size;
    const float* c      = (const float*)d_in[0];
    const float* q      = (const float*)d_in[1];
    const int*   c_mask = (const int*)d_in[2];
    const int*   q_mask = (const int*)d_in[3];
    const float* W      = (const float*)d_in[4];
    const float* bias   = (const float*)d_in[5];
    float* out = (float*)d_out;

    bq_kernel    <<<64, 256>>>(q, bias, 0);       // launch 0
    bq_kernel    <<<64, 256>>>(q, bias, 512);     // launch 1
    qp_gemm      <<<dim3(12, 16), 256>>>(q, W);   // launch 2
    s_gemm       <<<dim3(8, 16), 256>>>(c, q_mask); // launch 3  <- profiled slot
    colexp_kernel<<<16, 512>>>(c_mask);           // launch 4
    t_gemm       <<<dim3(12, 16), 256>>>(c);      // launch 5
    final_kernel <<<dim3(8, 16, 2), 256>>>(c, q, out); // launch 6
}

// round 8
// speedup vs baseline: 1.3766x; 1.0383x over previous
#include <cuda_runtime.h>
#include <float.h>

#define BB 16
#define CL 512
#define QL 64
#define HH 768
#define NEG_INF (-1e30f)

// ---------------- scratch ----------------
__device__ __align__(16) float g_qp[BB * QL * HH];   // q @ W            [B,64,768]
__device__ __align__(16) float g_bq[BB * QL];        // q . b            [B,64]
__device__ __align__(16) float g_s [BB * CL * QL];   // raw logits       [B,512,64]
__device__ __align__(16) float g_s1[BB * CL * QL];   // row softmax      [B,512,64]
__device__ __align__(16) float g_s2[BB * CL * QL];   // col exp (unnorm) [B,512,64]
__device__ __align__(16) float g_cinv[BB * QL];      // 1/col-sum        [B,64]
__device__ __align__(16) float g_t [BB * QL * HH];   // s2^T @ c         [B,64,768]

// ---------------- bq[row] = q[row,:] . b ----------------
__global__ void bq_kernel(const float* __restrict__ q, const float* __restrict__ bias,
                          int rowOffset) {
    int row  = rowOffset + blockIdx.x * 8 + (threadIdx.x >> 5);
    int lane = threadIdx.x & 31;
    const float* qr = q + row * HH;
    float s = 0.f;
    for (int d = lane; d < HH; d += 32) s += qr[d] * bias[d];
#pragma unroll
    for (int o = 16; o; o >>= 1) s += __shfl_down_sync(0xffffffffu, s, o);
    if (lane == 0) g_bq[row] = s;
}

// ---------------- qp = q @ W   (M=1024, N=768, K=768) ----------------
// 64x64x16 tiles, 256 thr, double-buffered, LDS.128 operands.
__global__ void qp_gemm(const float* __restrict__ q, const float* __restrict__ W) {
    __shared__ __align__(16) float As[2][16][68];   // [k][m]
    __shared__ __align__(16) float Bs[2][16][68];   // [k][n]
    int tid = threadIdx.x;
    int tx = tid & 15, ty = tid >> 4;
    int tx4 = tx << 2, ty4 = ty << 2;
    int mBase = blockIdx.y * 64, nBase = blockIdx.x * 64;
    int lm = tid >> 2, lk = (tid & 3) << 2;        // A fill (transpose)
    int bk = tid >> 4, bn4 = (tid & 15) << 2;      // B fill (direct)
    float acc[4][4] = {};

    float4 av = *(const float4*)(q + (mBase + lm) * HH + lk);
    float4 bv = *(const float4*)(W + bk * HH + nBase + bn4);
    As[0][lk + 0][lm] = av.x; As[0][lk + 1][lm] = av.y;
    As[0][lk + 2][lm] = av.z; As[0][lk + 3][lm] = av.w;
    *(float4*)&Bs[0][bk][bn4] = bv;
    __syncthreads();
    int buf = 0;
    for (int kt = 0; kt < HH; kt += 16) {
        bool more = (kt + 16) < HH;
        float4 nav, nbv;
        if (more) {
            nav = *(const float4*)(q + (mBase + lm) * HH + kt + 16 + lk);
            nbv = *(const float4*)(W + (kt + 16 + bk) * HH + nBase + bn4);
        }
#pragma unroll
        for (int k = 0; k < 16; k++) {
            float4 ar = *(const float4*)&As[buf][k][ty4];
            float4 br = *(const float4*)&Bs[buf][k][tx4];
            acc[0][0] = fmaf(ar.x, br.x, acc[0][0]); acc[0][1] = fmaf(ar.x, br.y, acc[0][1]);
            acc[0][2] = fmaf(ar.x, br.z, acc[0][2]); acc[0][3] = fmaf(ar.x, br.w, acc[0][3]);
            acc[1][0] = fmaf(ar.y, br.x, acc[1][0]); acc[1][1] = fmaf(ar.y, br.y, acc[1][1]);
            acc[1][2] = fmaf(ar.y, br.z, acc[1][2]); acc[1][3] = fmaf(ar.y, br.w, acc[1][3]);
            acc[2][0] = fmaf(ar.z, br.x, acc[2][0]); acc[2][1] = fmaf(ar.z, br.y, acc[2][1]);
            acc[2][2] = fmaf(ar.z, br.z, acc[2][2]); acc[2][3] = fmaf(ar.z, br.w, acc[2][3]);
            acc[3][0] = fmaf(ar.w, br.x, acc[3][0]); acc[3][1] = fmaf(ar.w, br.y, acc[3][1]);
            acc[3][2] = fmaf(ar.w, br.z, acc[3][2]); acc[3][3] = fmaf(ar.w, br.w, acc[3][3]);
        }
        if (more) {
            int nb = buf ^ 1;
            As[nb][lk + 0][lm] = nav.x; As[nb][lk + 1][lm] = nav.y;
            As[nb][lk + 2][lm] = nav.z; As[nb][lk + 3][lm] = nav.w;
            *(float4*)&Bs[nb][bk][bn4] = nbv;
            __syncthreads();
            buf = nb;
        }
    }
#pragma unroll
    for (int i = 0; i < 4; i++) {
        float4 o = make_float4(acc[i][0], acc[i][1], acc[i][2], acc[i][3]);
        *(float4*)(g_qp + (mBase + ty4 + i) * HH + nBase + tx4) = o;
    }
}

// ---------------- s_gemm + fused row softmax ----------------
// 32x64x16 tiles, 128 thr -> 256 CTAs (full SM coverage).
__global__ void s_gemm(const float* __restrict__ c, const int* __restrict__ q_mask) {
    __shared__ __align__(16) float As[2][16][36];   // c  [k][m], 32 rows
    __shared__ __align__(16) float Bs[2][16][68];   // qp [k][j]
    int tid = threadIdx.x;
    int tx = tid & 15, ty = tid >> 4;              // ty 0..7
    int tx4 = tx << 2, ty4 = ty << 2;              // rows ty4..ty4+3 (0..31)
    int b = blockIdx.y;
    int mBase = blockIdx.x * 32;
    const float* A = c + b * CL * HH;
    const float* Bt = g_qp + b * QL * HH;
    int lm = tid >> 2, lk = (tid & 3) << 2;        // A fill: 32 rows x 16k / 128thr
    int lj = tid >> 1, lkb = (tid & 1) << 3;       // B fill: 64 j x 16k, 8 floats/thr
    float acc[4][4] = {};

    {
        float4 av = *(const float4*)(A + (mBase + lm) * HH + lk);
        As[0][lk + 0][lm] = av.x; As[0][lk + 1][lm] = av.y;
        As[0][lk + 2][lm] = av.z; As[0][lk + 3][lm] = av.w;
        float4 b1 = *(const float4*)(Bt + lj * HH + lkb);
        float4 b2 = *(const float4*)(Bt + lj * HH + lkb + 4);
        Bs[0][lkb + 0][lj] = b1.x; Bs[0][lkb + 1][lj] = b1.y;
        Bs[0][lkb + 2][lj] = b1.z; Bs[0][lkb + 3][lj] = b1.w;
        Bs[0][lkb + 4][lj] = b2.x; Bs[0][lkb + 5][lj] = b2.y;
        Bs[0][lkb + 6][lj] = b2.z; Bs[0][lkb + 7][lj] = b2.w;
    }
    __syncthreads();
    int buf = 0;
    for (int kt = 0; kt < HH; kt += 16) {
        bool more = (kt + 16) < HH;
        float4 nav, nb1, nb2;
        if (more) {
            nav = *(const float4*)(A + (mBase + lm) * HH + kt + 16 + lk);
            nb1 = *(const float4*)(Bt + lj * HH + kt + 16 + lkb);
            nb2 = *(const float4*)(Bt + lj * HH + kt + 16 + lkb + 4);
        }
#pragma unroll
        for (int k = 0; k < 16; k++) {
            float4 ar = *(const float4*)&As[buf][k][ty4];
            float4 br = *(const float4*)&Bs[buf][k][tx4];
            acc[0][0] = fmaf(ar.x, br.x, acc[0][0]); acc[0][1] = fmaf(ar.x, br.y, acc[0][1]);
            acc[0][2] = fmaf(ar.x, br.z, acc[0][2]); acc[0][3] = fmaf(ar.x, br.w, acc[0][3]);
            acc[1][0] = fmaf(ar.y, br.x, acc[1][0]); acc[1][1] = fmaf(ar.y, br.y, acc[1][1]);
            acc[1][2] = fmaf(ar.y, br.z, acc[1][2]); acc[1][3] = fmaf(ar.y, br.w, acc[1][3]);
            acc[2][0] = fmaf(ar.z, br.x, acc[2][0]); acc[2][1] = fmaf(ar.z, br.y, acc[2][1]);
            acc[2][2] = fmaf(ar.z, br.z, acc[2][2]); acc[2][3] = fmaf(ar.z, br.w, acc[2][3]);
            acc[3][0] = fmaf(ar.w, br.x, acc[3][0]); acc[3][1] = fmaf(ar.w, br.y, acc[3][1]);
            acc[3][2] = fmaf(ar.w, br.z, acc[3][2]); acc[3][3] = fmaf(ar.w, br.w, acc[3][3]);
        }
        if (more) {
            int nb = buf ^ 1;
            As[nb][lk + 0][lm] = nav.x; As[nb][lk + 1][lm] = nav.y;
            As[nb][lk + 2][lm] = nav.z; As[nb][lk + 3][lm] = nav.w;
            Bs[nb][lkb + 0][lj] = nb1.x; Bs[nb][lkb + 1][lj] = nb1.y;
            Bs[nb][lkb + 2][lj] = nb1.z; Bs[nb][lkb + 3][lj] = nb1.w;
            Bs[nb][lkb + 4][lj] = nb2.x; Bs[nb][lkb + 5][lj] = nb2.y;
            Bs[nb][lkb + 6][lj] = nb2.z; Bs[nb][lkb + 7][lj] = nb2.w;
            __syncthreads();
            buf = nb;
        }
    }
    // epilogue: bias, raw store, fused row softmax (16 threads own each row).
    float4 bqv = *(const float4*)(g_bq + b * QL + tx4);
    int qm0 = q_mask[b * QL + tx4 + 0];
    int qm1 = q_mask[b * QL + tx4 + 1];
    int qm2 = q_mask[b * QL + tx4 + 2];
    int qm3 = q_mask[b * QL + tx4 + 3];
#pragma unroll
    for (int i = 0; i < 4; i++) {
        float v0 = acc[i][0] + bqv.x, v1 = acc[i][1] + bqv.y;
        float v2 = acc[i][2] + bqv.z, v3 = acc[i][3] + bqv.w;
        int row = b * CL + mBase + ty4 + i;
        *(float4*)(g_s + row * QL + tx4) = make_float4(v0, v1, v2, v3);
        float m0 = qm0 ? v0 : NEG_INF;
        float m1 = qm1 ? v1 : NEG_INF;
        float m2 = qm2 ? v2 : NEG_INF;
        float m3 = qm3 ? v3 : NEG_INF;
        float mx = fmaxf(fmaxf(m0, m1), fmaxf(m2, m3));
#pragma unroll
        for (int o = 8; o; o >>= 1) mx = fmaxf(mx, __shfl_xor_sync(0xffffffffu, mx, o));
        float e0 = __expf(m0 - mx), e1 = __expf(m1 - mx);
        float e2 = __expf(m2 - mx), e3 = __expf(m3 - mx);
        float s = e0 + e1 + e2 + e3;
#pragma unroll
        for (int o = 8; o; o >>= 1) s += __shfl_xor_sync(0xffffffffu, s, o);
        float inv = 1.f / s;
        *(float4*)(g_s1 + row * QL + tx4) = make_float4(e0 * inv, e1 * inv, e2 * inv, e3 * inv);
    }
}

// ---------------- colexp: per-batch column max + exp + 1/sum ----------------
__global__ void colexp_kernel(const int* __restrict__ c_mask) {
    int b = blockIdx.x;
    int tid = threadIdx.x;              // 0..511
    int cg = tid & 15;
    int ry = tid >> 4;                  // 0..31
    __shared__ float4 red[32][16];
    const float* sp = g_s + b * CL * QL;
    const int*   mp = c_mask + b * CL;

    float4 mx = make_float4(NEG_INF, NEG_INF, NEG_INF, NEG_INF);
#pragma unroll
    for (int k = 0; k < 16; k++) {
        int r = ry + k * 32;
        float4 v = *(const float4*)(sp + r * QL + cg * 4);
        if (!mp[r]) v = make_float4(NEG_INF, NEG_INF, NEG_INF, NEG_INF);
        mx.x = fmaxf(mx.x, v.x); mx.y = fmaxf(mx.y, v.y);
        mx.z = fmaxf(mx.z, v.z); mx.w = fmaxf(mx.w, v.w);
    }
    red[ry][cg] = mx;
    __syncthreads();
#pragma unroll
    for (int st = 16; st >= 1; st >>= 1) {
        if (ry < st) {
            float4 a = red[ry][cg], c2 = red[ry + st][cg];
            a.x = fmaxf(a.x, c2.x); a.y = fmaxf(a.y, c2.y);
            a.z = fmaxf(a.z, c2.z); a.w = fmaxf(a.w, c2.w);
            red[ry][cg] = a;
        }
        __syncthreads();
    }
    float4 cmax = red[0][cg];
    __syncthreads();

    float4 sm = make_float4(0.f, 0.f, 0.f, 0.f);
    float* op = g_s2 + b * CL * QL;
#pragma unroll
    for (int k = 0; k < 16; k++) {
        int r = ry + k * 32;
        float4 v = *(const float4*)(sp + r * QL + cg * 4);
        if (!mp[r]) v = make_float4(NEG_INF, NEG_INF, NEG_INF, NEG_INF);
        float4 e;
        e.x = __expf(v.x - cmax.x); e.y = __expf(v.y - cmax.y);
        e.z = __expf(v.z - cmax.z); e.w = __expf(v.w - cmax.w);
        *(float4*)(op + r * QL + cg * 4) = e;
        sm.x += e.x; sm.y += e.y; sm.z += e.z; sm.w += e.w;
    }
    red[ry][cg] = sm;
    __syncthreads();
#pragma unroll
    for (int st = 16; st >= 1; st >>= 1) {
        if (ry < st) {
            float4 a = red[ry][cg], c2 = red[ry + st][cg];
            a.x += c2.x; a.y += c2.y; a.z += c2.z; a.w += c2.w;
            red[ry][cg] = a;
        }
        __syncthreads();
    }
    if (ry == 0) {
        float4 s = red[0][cg];
        float4 inv = make_float4(1.f / s.x, 1.f / s.y, 1.f / s.z, 1.f / s.w);
        *(float4*)(g_cinv + b * QL + cg * 4) = inv;
    }
}

// ---------------- t[b,j,h] = sum_c s2n[b,c,j] * c[b,c,h]  (M=64, N=768, K=512) ----------------
__global__ void t_gemm(const float* __restrict__ c) {
    __shared__ __align__(16) float As[2][16][68];   // [kc][j], scaled
    __shared__ __align__(16) float Bs[2][16][68];   // [kc][h]
    int tid = threadIdx.x;
    int tx = tid & 15, ty = tid >> 4;
    int tx4 = tx << 2, ty4 = ty << 2;
    int b = blockIdx.y;
    int nBase = blockIdx.x * 64;
    int lc = tid >> 4, lj4 = (tid & 15) << 2;
    int bk = tid >> 4, bn4 = (tid & 15) << 2;
    float4 inv4 = *(const float4*)(g_cinv + b * QL + lj4);
    float acc[4][4] = {};

    float4 av = *(const float4*)(g_s2 + (b * CL + lc) * QL + lj4);
    av.x *= inv4.x; av.y *= inv4.y; av.z *= inv4.z; av.w *= inv4.w;
    float4 bv = *(const float4*)(c + (b * CL + bk) * HH + nBase + bn4);
    *(float4*)&As[0][lc][lj4] = av;
    *(float4*)&Bs[0][bk][bn4] = bv;
    __syncthreads();
    int buf = 0;
    for (int kt = 0; kt < CL; kt += 16) {
        bool more = (kt + 16) < CL;
        float4 nav, nbv;
        if (more) {
            nav = *(const float4*)(g_s2 + (b * CL + kt + 16 + lc) * QL + lj4);
            nav.x *= inv4.x; nav.y *= inv4.y; nav.z *= inv4.z; nav.w *= inv4.w;
            nbv = *(const float4*)(c + (b * CL + kt + 16 + bk) * HH + nBase + bn4);
        }
#pragma unroll
        for (int k = 0; k < 16; k++) {
            float4 ar = *(const float4*)&As[buf][k][ty4];
            float4 br = *(const float4*)&Bs[buf][k][tx4];
            acc[0][0] = fmaf(ar.x, br.x, acc[0][0]); acc[0][1] = fmaf(ar.x, br.y, acc[0][1]);
            acc[0][2] = fmaf(ar.x, br.z, acc[0][2]); acc[0][3] = fmaf(ar.x, br.w, acc[0][3]);
            acc[1][0] = fmaf(ar.y, br.x, acc[1][0]); acc[1][1] = fmaf(ar.y, br.y, acc[1][1]);
            acc[1][2] = fmaf(ar.y, br.z, acc[1][2]); acc[1][3] = fmaf(ar.y, br.w, acc[1][3]);
            acc[2][0] = fmaf(ar.z, br.x, acc[2][0]); acc[2][1] = fmaf(ar.z, br.y, acc[2][1]);
            acc[2][2] = fmaf(ar.z, br.z, acc[2][2]); acc[2][3] = fmaf(ar.z, br.w, acc[2][3]);
            acc[3][0] = fmaf(ar.w, br.x, acc[3][0]); acc[3][1] = fmaf(ar.w, br.y, acc[3][1]);
            acc[3][2] = fmaf(ar.w, br.z, acc[3][2]); acc[3][3] = fmaf(ar.w, br.w, acc[3][3]);
        }
        if (more) {
            int nb = buf ^ 1;
            *(float4*)&As[nb][lc][lj4] = nav;
            *(float4*)&Bs[nb][bk][bn4] = nbv;
            __syncthreads();
            buf = nb;
        }
    }
#pragma unroll
    for (int i = 0; i < 4; i++) {
        float4 o = make_float4(acc[i][0], acc[i][1], acc[i][2], acc[i][3]);
        *(float4*)(g_t + (b * QL + ty4 + i) * HH + nBase + tx4) = o;
    }
}

// ---------------- final: a = s1@q, bvec = s1@t, out = [c, a, c*a, c*bvec] ----------------
// S1 stored TRANSPOSED (S1T[j][c]) so both operands are LDS.128.
__global__ void final_kernel(const float* __restrict__ c, const float* __restrict__ q,
                             float* __restrict__ out) {
    __shared__ __align__(16) float S1T[64][68];  // [j][c]
    __shared__ __align__(16) float Buf[64][68];  // [j][h]
    int tid = threadIdx.x;
    int tx = tid & 15, ty = tid >> 4;
    int tx4 = tx << 2, ty4 = ty << 2;
    int b = blockIdx.y;
    int cBase = blockIdx.x * 64;
    int hStart = blockIdx.z * 384;

    int lr  = tid >> 2;            // 0..63
    int lcb = (tid & 3) << 2;      // 0,4,8,12

#pragma unroll
    for (int i = 0; i < 4; i++) {
        int lc = lcb + i * 16;
        float4 sv = *(const float4*)(g_s1 + (b * CL + cBase + lr) * QL + lc);
        S1T[lc + 0][lr] = sv.x; S1T[lc + 1][lr] = sv.y;
        S1T[lc + 2][lr] = sv.z; S1T[lc + 3][lr] = sv.w;
    }
    __syncthreads();

    const float* qb = q + b * QL * HH;
    const float* tb = g_t + b * QL * HH;
    const float* cb = c + b * CL * HH;
    float* ob = out + (size_t)(b * CL) * (4 * HH);

    for (int hc = hStart; hc < hStart + 384; hc += 64) {
        // ---- pass 1: a = s1 @ q ----
#pragma unroll
        for (int i = 0; i < 4; i++) {
            int lc = lcb + i * 16;
            float4 qv = *(const float4*)(qb + lr * HH + hc + lc);
            Buf[lr][lc + 0] = qv.x; Buf[lr][lc + 1] = qv.y;
            Buf[lr][lc + 2] = qv.z; Buf[lr][lc + 3] = qv.w;
        }
        __syncthreads();
        float acc[4][4] = {};
#pragma unroll 16
        for (int k = 0; k < 64; k++) {
            float4 ar = *(const float4*)&S1T[k][ty4];
            float4 br = *(const float4*)&Buf[k][tx4];
            acc[0][0] = fmaf(ar.x, br.x, acc[0][0]); acc[0][1] = fmaf(ar.x, br.y, acc[0][1]);
            acc[0][2] = fmaf(ar.x, br.z, acc[0][2]); acc[0][3] = fmaf(ar.x, br.w, acc[0][3]);
            acc[1][0] = fmaf(ar.y, br.x, acc[1][0]); acc[1][1] = fmaf(ar.y, br.y, acc[1][1]);
            acc[1][2] = fmaf(ar.y, br.z, acc[1][2]); acc[1][3] = fmaf(ar.y, br.w, acc[1][3]);
            acc[2][0] = fmaf(ar.z, br.x, acc[2][0]); acc[2][1] = fmaf(ar.z, br.y, acc[2][1]);
            acc[2][2] = fmaf(ar.z, br.z, acc[2][2]); acc[2][3] = fmaf(ar.z, br.w, acc[2][3]);
            acc[3][0] = fmaf(ar.w, br.x, acc[3][0]); acc[3][1] = fmaf(ar.w, br.y, acc[3][1]);
            acc[3][2] = fmaf(ar.w, br.z, acc[3][2]); acc[3][3] = fmaf(ar.w, br.w, acc[3][3]);
        }
#pragma unroll
        for (int i = 0; i < 4; i++) {
            int r = cBase + ty4 + i;
            float4 cv = *(const float4*)(cb + r * HH + hc + tx4);
            float4 a4 = make_float4(acc[i][0], acc[i][1], acc[i][2], acc[i][3]);
            float4 ca = make_float4(cv.x * a4.x, cv.y * a4.y, cv.z * a4.z, cv.w * a4.w);
            float* orow = ob + (size_t)r * (4 * HH);
            *(float4*)(orow + 0 * HH + hc + tx4) = cv;   // c
            *(float4*)(orow + 1 * HH + hc + tx4) = a4;   // a
            *(float4*)(orow + 2 * HH + hc + tx4) = ca;   // c*a
        }
        __syncthreads();
        // ---- pass 2: bvec = s1 @ t ----
#pragma unroll
        for (int i = 0; i < 4; i++) {
            int lc = lcb + i * 16;
            float4 tv = *(const float4*)(tb + lr * HH + hc + lc);
            Buf[lr][lc + 0] = tv.x; Buf[lr][lc + 1] = tv.y;
            Buf[lr][lc + 2] = tv.z; Buf[lr][lc + 3] = tv.w;
        }
        __syncthreads();
        float acc2[4][4] = {};
#pragma unroll 16
        for (int k = 0; k < 64; k++) {
            float4 ar = *(const float4*)&S1T[k][ty4];
            float4 br = *(const float4*)&Buf[k][tx4];
            acc2[0][0] = fmaf(ar.x, br.x, acc2[0][0]); acc2[0][1] = fmaf(ar.x, br.y, acc2[0][1]);
            acc2[0][2] = fmaf(ar.x, br.z, acc2[0][2]); acc2[0][3] = fmaf(ar.x, br.w, acc2[0][3]);
            acc2[1][0] = fmaf(ar.y, br.x, acc2[1][0]); acc2[1][1] = fmaf(ar.y, br.y, acc2[1][1]);
            acc2[1][2] = fmaf(ar.y, br.z, acc2[1][2]); acc2[1][3] = fmaf(ar.y, br.w, acc2[1][3]);
            acc2[2][0] = fmaf(ar.z, br.x, acc2[2][0]); acc2[2][1] = fmaf(ar.z, br.y, acc2[2][1]);
            acc2[2][2] = fmaf(ar.z, br.z, acc2[2][2]); acc2[2][3] = fmaf(ar.z, br.w, acc2[2][3]);
            acc2[3][0] = fmaf(ar.w, br.x, acc2[3][0]); acc2[3][1] = fmaf(ar.w, br.y, acc2[3][1]);
            acc2[3][2] = fmaf(ar.w, br.z, acc2[3][2]); acc2[3][3] = fmaf(ar.w, br.w, acc2[3][3]);
        }
#pragma unroll
        for (int i = 0; i < 4; i++) {
            int r = cBase + ty4 + i;
            float4 cv = *(const float4*)(cb + r * HH + hc + tx4);
            float4 cbv = make_float4(cv.x * acc2[i][0], cv.y * acc2[i][1],
                                     cv.z * acc2[i][2], cv.w * acc2[i][3]);
            float* orow = ob + (size_t)r * (4 * HH);
            *(float4*)(orow + 3 * HH + hc + tx4) = cbv;  // c*bvec
        }
        __syncthreads();
    }
}

extern "C" void kernel_launch(void* const* d_in, const int* in_sizes, int n_in,
                              void* d_out, int out_size) {
    (void)in_sizes; (void)n_in; (void)out_size;
    const float* c      = (const float*)d_in[0];
    const float* q      = (const float*)d_in[1];
    const int*   c_mask = (const int*)d_in[2];
    const int*   q_mask = (const int*)d_in[3];
    const float* W      = (const float*)d_in[4];
    const float* bias   = (const float*)d_in[5];
    float* out = (float*)d_out;

    bq_kernel    <<<64, 256>>>(q, bias, 0);
    bq_kernel    <<<64, 256>>>(q, bias, 512);
    qp_gemm      <<<dim3(12, 16), 256>>>(q, W);
    s_gemm       <<<dim3(16, 16), 128>>>(c, q_mask);
    colexp_kernel<<<16, 512>>>(c_mask);
    t_gemm       <<<dim3(12, 16), 256>>>(c);
    final_kernel <<<dim3(8, 16, 2), 256>>>(c, q, out);
}